// round 8
// baseline (speedup 1.0000x reference)
#include <cuda_runtime.h>

#define TDIM 512
#define IDIM 512
#define HDIM 1024
#define G4   4096
#define NBLK 128
#define KP   1040            // hsm row stride (floats)

typedef unsigned long long ull;

__device__ float g_xg[(size_t)32 * TDIM * G4];   // [B,T,4H]
__device__ float g_hbk[2][32 * HDIM];            // h as [b][k]
__device__ int   g_count;

__device__ __forceinline__ ull ffma2(ull a, ull b, ull c) {
    ull d; asm("fma.rn.f32x2 %0, %1, %2, %3;" : "=l"(d) : "l"(a), "l"(b), "l"(c));
    return d;
}
__device__ __forceinline__ ull add2(ull a, ull b) {
    ull d; asm("add.rn.f32x2 %0, %1, %2;" : "=l"(d) : "l"(a), "l"(b));
    return d;
}
__device__ __forceinline__ ull pack2(float x, float y) {
    ull d; asm("mov.b64 %0, {%1, %2};" : "=l"(d) : "f"(x), "f"(y));
    return d;
}
__device__ __forceinline__ float2 unpack2(ull v) {
    float2 r; asm("mov.b64 {%0, %1}, %2;" : "=f"(r.x), "=f"(r.y) : "l"(v));
    return r;
}
__device__ __forceinline__ int ld_acquire(const int* p) {
    int v; asm volatile("ld.global.acquire.gpu.b32 %0, [%1];" : "=r"(v) : "l"(p));
    return v;
}

__global__ void init_state_kernel() {
    int i = blockIdx.x * blockDim.x + threadIdx.x;
    if (i < 32 * HDIM) g_hbk[0][i] = 0.0f;
    if (i == 0) g_count = 0;
}

// Phase 1 GEMM (f32x2): xg[16384,4096] = X*Wx^T + (bx+bh)
__global__ void __launch_bounds__(256, 2) gemm_xg_kernel(
    const float* __restrict__ X, const float* __restrict__ Wx,
    const float* __restrict__ bx, const float* __restrict__ bh)
{
    __shared__ float As[16][128];
    __shared__ float Bs[16][128];
    const int tid = threadIdx.x;
    const int bm = blockIdx.y * 128, bn = blockIdx.x * 128;
    const int lr = tid >> 2, lc = (tid & 3) << 2;
    const int tm = (tid >> 4) << 3, tn = (tid & 15) << 3;

    ull acc2[4][8];
#pragma unroll
    for (int i = 0; i < 4; i++)
#pragma unroll
        for (int j = 0; j < 8; j++) acc2[i][j] = 0ULL;

    for (int k0 = 0; k0 < IDIM; k0 += 16) {
#pragma unroll
        for (int r = 0; r < 2; r++) {
            const int row = lr + r * 64;
            float4 va = *(const float4*)(X  + (size_t)(bm + row) * IDIM + k0 + lc);
            As[lc+0][row]=va.x; As[lc+1][row]=va.y; As[lc+2][row]=va.z; As[lc+3][row]=va.w;
            float4 vb = *(const float4*)(Wx + (size_t)(bn + row) * IDIM + k0 + lc);
            Bs[lc+0][row]=vb.x; Bs[lc+1][row]=vb.y; Bs[lc+2][row]=vb.z; Bs[lc+3][row]=vb.w;
        }
        __syncthreads();
#pragma unroll
        for (int kk = 0; kk < 16; kk++) {
            const ull* ap = (const ull*)(&As[kk][tm]);
            ull a2[4] = {ap[0], ap[1], ap[2], ap[3]};
            float4 b0 = *(const float4*)(&Bs[kk][tn]);
            float4 b1 = *(const float4*)(&Bs[kk][tn + 4]);
            ull bd[8];
            bd[0]=pack2(b0.x,b0.x); bd[1]=pack2(b0.y,b0.y);
            bd[2]=pack2(b0.z,b0.z); bd[3]=pack2(b0.w,b0.w);
            bd[4]=pack2(b1.x,b1.x); bd[5]=pack2(b1.y,b1.y);
            bd[6]=pack2(b1.z,b1.z); bd[7]=pack2(b1.w,b1.w);
#pragma unroll
            for (int ip = 0; ip < 4; ip++)
#pragma unroll
                for (int j = 0; j < 8; j++)
                    acc2[ip][j] = ffma2(a2[ip], bd[j], acc2[ip][j]);
        }
        __syncthreads();
    }
    float bias[8];
#pragma unroll
    for (int j = 0; j < 8; j++) bias[j] = bx[bn + tn + j] + bh[bn + tn + j];
#pragma unroll
    for (int ip = 0; ip < 4; ip++) {
        float lo[8], hi[8];
#pragma unroll
        for (int j = 0; j < 8; j++) {
            float2 v = unpack2(acc2[ip][j]);
            lo[j] = v.x + bias[j]; hi[j] = v.y + bias[j];
        }
        float* o0 = g_xg + (size_t)(bm + tm + 2*ip)     * G4 + bn + tn;
        float* o1 = g_xg + (size_t)(bm + tm + 2*ip + 1) * G4 + bn + tn;
        *(float4*)(o0)   = make_float4(lo[0],lo[1],lo[2],lo[3]);
        *(float4*)(o0+4) = make_float4(lo[4],lo[5],lo[6],lo[7]);
        *(float4*)(o1)   = make_float4(hi[0],hi[1],hi[2],hi[3]);
        *(float4*)(o1+4) = make_float4(hi[4],hi[5],hi[6],hi[7]);
    }
}

// Phase 2: persistent recurrence. warp=cell, lane=k-slice (quads).
// Weights as k-pair f32x2 per gate in regs; h in smem [b][k]: one LDS.128
// yields two ready f32x2 operands (zero packing MOVs in the hot loop).
#define RED(m, hw)                                                            \
    { const bool hb = (l & m);                                                \
      _Pragma("unroll")                                                       \
      for (int j = 0; j < hw; j++) {                                          \
          ull mine = hb ? A[j + hw] : A[j];                                   \
          ull oth  = hb ? A[j] : A[j + hw];                                   \
          A[j] = add2(mine, __shfl_xor_sync(0xffffffffu, oth, m));            \
      } }

__global__ void __launch_bounds__(256, 1) lstm_persistent_kernel(
    const float* __restrict__ Wh, float* __restrict__ out)
{
    extern __shared__ float hsm[];               // [32][KP]
    const int tid = threadIdx.x;
    const int l = tid & 31, w = tid >> 5;
    const int n = blockIdx.x * 8 + w;

    // weights: lane owns k in {128q + 4l + e}, packed as k-pairs per gate
    ull wreg[4][16];
#pragma unroll
    for (int g = 0; g < 4; g++)
#pragma unroll
        for (int q = 0; q < 8; q++) {
            const float* wr = Wh + (size_t)(n + g * HDIM) * HDIM + (q << 7) + (l << 2);
            wreg[g][2*q]   = pack2(wr[0], wr[1]);
            wreg[g][2*q+1] = pack2(wr[2], wr[3]);
        }

    const int gate = l & 3, bsub = l >> 2, gbase = l & ~3;
    const bool isG = (gate == 2);
    const int sb = tid >> 3, sc = tid & 7;
    const unsigned sbase = (unsigned)__cvta_generic_to_shared(hsm);
    float cst[4] = {0.f, 0.f, 0.f, 0.f};

    for (int t = 0; t < TDIM; t++) {
        const float* src = g_hbk[t & 1] + (size_t)sb * HDIM + (sc << 2);
#pragma unroll
        for (int r = 0; r < 32; r++) {
            const unsigned d = sbase + (unsigned)(sb * KP + ((sc + (r << 3)) << 2)) * 4u;
            asm volatile("cp.async.cg.shared.global [%0], [%1], 16;"
                         :: "r"(d), "l"(src + (r << 5)) : "memory");
        }
        asm volatile("cp.async.commit_group;" ::: "memory");

        float xgv[4];
#pragma unroll
        for (int p = 0; p < 4; p++)
            xgv[p] = __ldg(g_xg + ((size_t)(p*8 + bsub) * TDIM + t) * G4
                           + (size_t)gate * HDIM + n);

        asm volatile("cp.async.wait_group 0;" ::: "memory");
        __syncthreads();

#pragma unroll
        for (int p = 0; p < 4; p++) {
            ull A[32];
#pragma unroll
            for (int v = 0; v < 32; v++) A[v] = 0ULL;

#pragma unroll
            for (int b = 0; b < 8; b++) {
                const float* hp = hsm + (p*8 + b) * KP + (l << 2);
#pragma unroll
                for (int q = 0; q < 8; q++) {
                    const float4 h4 = *(const float4*)(hp + (q << 7));
                    const ull h01 = ((const ull*)&h4)[0];
                    const ull h23 = ((const ull*)&h4)[1];
#pragma unroll
                    for (int g = 0; g < 4; g++) {
                        A[(b<<2)|g] = ffma2(h01, wreg[g][2*q],   A[(b<<2)|g]);
                        A[(b<<2)|g] = ffma2(h23, wreg[g][2*q+1], A[(b<<2)|g]);
                    }
                }
            }

            RED(16, 16) RED(8, 8) RED(4, 4) RED(2, 2) RED(1, 1)

            const float2 y = unpack2(A[0]);
            float F = y.x + y.y + xgv[p];
            float a = tanhf(isG ? F : 0.5f * F);
            a = isG ? a : 0.5f * (1.0f + a);

            const float vi = __shfl_sync(0xffffffffu, a, gbase);
            const float vf = __shfl_sync(0xffffffffu, a, gbase + 1);
            const float vg = __shfl_sync(0xffffffffu, a, gbase + 2);
            const float vo = __shfl_sync(0xffffffffu, a, gbase + 3);

            cst[p] = vf * cst[p] + vi * vg;
            const float h = vo * tanhf(cst[p]);

            if (gate == 0) {
                const int bb = p*8 + bsub;
                g_hbk[(t + 1) & 1][bb * HDIM + n] = h;
                out[((size_t)bb * TDIM + t) * HDIM + n] = h;
            }
        }

        if (t < TDIM - 1) {
            __threadfence();
            __syncthreads();
            if (tid == 0) {
                atomicAdd(&g_count, 1);
                while (ld_acquire(&g_count) < NBLK * (t + 1)) { }
            }
            __syncthreads();
        }
    }
}

extern "C" void kernel_launch(void* const* d_in, const int* in_sizes, int n_in,
                              void* d_out, int out_size)
{
    const float* x  = (const float*)d_in[0];
    const float* Wx = (const float*)d_in[1];
    const float* bx = (const float*)d_in[2];
    const float* Wh = (const float*)d_in[3];
    const float* bh = (const float*)d_in[4];
    float* out = (float*)d_out;
    (void)in_sizes; (void)n_in; (void)out_size;

    const int SMEM_BYTES = 32 * KP * (int)sizeof(float);   // 133120
    cudaFuncSetAttribute(lstm_persistent_kernel,
                         cudaFuncAttributeMaxDynamicSharedMemorySize, SMEM_BYTES);

    init_state_kernel<<<(32 * HDIM + 255) / 256, 256>>>();

    dim3 ggrid(G4 / 128, (32 * TDIM) / 128);
    gemm_xg_kernel<<<ggrid, 256>>>(x, Wx, bx, bh);

    lstm_persistent_kernel<<<NBLK, 256, SMEM_BYTES>>>(Wh, out);
}

// round 10
// speedup vs baseline: 1.4018x; 1.4018x over previous
#include <cuda_runtime.h>
#include <cuda_bf16.h>
#include <cstdint>

#define TDIM 512
#define IDIM 512
#define HDIM 1024
#define G4   4096
#define NBLK 128
#define BBUF0 131072
#define BBUF1 163840
#define DSMOFF 196608
#define SMEM_SZ 200960

typedef unsigned long long ull;

__device__ float g_xg[(size_t)32 * TDIM * G4];                 // [B,T,4H]
__device__ __align__(128) unsigned char g_W[(size_t)NBLK * 131072]; // per blk: Whi 64K | Wlo 64K
__device__ __align__(128) unsigned char g_hB[2][131072];       // h tiles: hi 64K | lo 64K
__device__ int g_count;

__device__ __forceinline__ ull ffma2(ull a, ull b, ull c) {
    ull d; asm("fma.rn.f32x2 %0, %1, %2, %3;" : "=l"(d) : "l"(a), "l"(b), "l"(c));
    return d;
}
__device__ __forceinline__ ull pack2(float x, float y) {
    ull d; asm("mov.b64 %0, {%1, %2};" : "=l"(d) : "f"(x), "f"(y));
    return d;
}
__device__ __forceinline__ float2 unpack2(ull v) {
    float2 r; asm("mov.b64 {%0, %1}, %2;" : "=f"(r.x), "=f"(r.y) : "l"(v));
    return r;
}
__device__ __forceinline__ int ld_acquire(const int* p) {
    int v; asm volatile("ld.global.acquire.gpu.b32 %0, [%1];" : "=r"(v) : "l"(p));
    return v;
}
__device__ __forceinline__ void ldsm4(uint32_t a, uint32_t* r) {
    asm volatile("ldmatrix.sync.aligned.m8n8.x4.shared.b16 {%0,%1,%2,%3}, [%4];"
        : "=r"(r[0]), "=r"(r[1]), "=r"(r[2]), "=r"(r[3]) : "r"(a));
}
__device__ __forceinline__ void ldsm2t(uint32_t a, uint32_t* r) {
    asm volatile("ldmatrix.sync.aligned.m8n8.x2.trans.shared.b16 {%0,%1}, [%2];"
        : "=r"(r[0]), "=r"(r[1]) : "r"(a));
}
__device__ __forceinline__ void hmma(float* d, const uint32_t* a, const uint32_t* b) {
    asm volatile("mma.sync.aligned.m16n8k16.row.col.f32.bf16.bf16.f32 "
        "{%0,%1,%2,%3},{%4,%5,%6,%7},{%8,%9},{%0,%1,%2,%3};"
        : "+f"(d[0]), "+f"(d[1]), "+f"(d[2]), "+f"(d[3])
        : "r"(a[0]), "r"(a[1]), "r"(a[2]), "r"(a[3]), "r"(b[0]), "r"(b[1]));
}
__device__ __forceinline__ void cpa(uint32_t d, const void* s) {
    asm volatile("cp.async.cg.shared.global [%0], [%1], 16;" :: "r"(d), "l"(s) : "memory");
}

// ---- one-time: split Wh -> bf16 hi/lo tile images (ldmatrix-swizzled) -----
__global__ void __launch_bounds__(256) prep_kernel(const float* __restrict__ Wh) {
    const int e = blockIdx.x * 256 + threadIdx.x;        // 2,097,152
    const int blk = e >> 14, rem = e & 16383;
    const int m = rem >> 9, k = (rem & 511) * 2;
    const int row = ((m >> 3) << 10) + (blk << 3) + (m & 7);
    const float2 wv = *(const float2*)(Wh + (size_t)row * HDIM + k);
    __nv_bfloat16 h0 = __float2bfloat16(wv.x), h1 = __float2bfloat16(wv.y);
    __nv_bfloat16 l0 = __float2bfloat16(wv.x - __bfloat162float(h0));
    __nv_bfloat16 l1 = __float2bfloat16(wv.y - __bfloat162float(h1));
    const uint32_t hi = (uint32_t)*(unsigned short*)&h0 | ((uint32_t)*(unsigned short*)&h1 << 16);
    const uint32_t lo = (uint32_t)*(unsigned short*)&l0 | ((uint32_t)*(unsigned short*)&l1 << 16);
    const int mt = m >> 4, r = m & 15, kt = k >> 4, kc = k & 15;
    const uint32_t off = (uint32_t)(mt * 32768 + kt * 512 + r * 32
                       + (((kc >> 3) ^ ((r >> 2) & 1)) << 4) + (kc & 7) * 2);
    unsigned char* base = g_W + (size_t)blk * 131072;
    *(uint32_t*)(base + off) = hi;
    *(uint32_t*)(base + 65536 + off) = lo;
    if (e < 32768) ((uint32_t*)g_hB[0])[e] = 0u;
    if (e == 0) g_count = 0;
}

// ---- Phase 1 GEMM (fp32x2, unchanged) -------------------------------------
__global__ void __launch_bounds__(256, 2) gemm_xg_kernel(
    const float* __restrict__ X, const float* __restrict__ Wx,
    const float* __restrict__ bx, const float* __restrict__ bh)
{
    __shared__ float As[16][128];
    __shared__ float Bs[16][128];
    const int tid = threadIdx.x;
    const int bm = blockIdx.y * 128, bn = blockIdx.x * 128;
    const int lr = tid >> 2, lc = (tid & 3) << 2;
    const int tm = (tid >> 4) << 3, tn = (tid & 15) << 3;

    ull acc2[4][8];
#pragma unroll
    for (int i = 0; i < 4; i++)
#pragma unroll
        for (int j = 0; j < 8; j++) acc2[i][j] = 0ULL;

    for (int k0 = 0; k0 < IDIM; k0 += 16) {
#pragma unroll
        for (int r = 0; r < 2; r++) {
            const int row = lr + r * 64;
            float4 va = *(const float4*)(X + (size_t)(bm + row) * IDIM + k0 + lc);
            As[lc+0][row]=va.x; As[lc+1][row]=va.y; As[lc+2][row]=va.z; As[lc+3][row]=va.w;
            float4 vb = *(const float4*)(Wx + (size_t)(bn + row) * IDIM + k0 + lc);
            Bs[lc+0][row]=vb.x; Bs[lc+1][row]=vb.y; Bs[lc+2][row]=vb.z; Bs[lc+3][row]=vb.w;
        }
        __syncthreads();
#pragma unroll
        for (int kk = 0; kk < 16; kk++) {
            const ull* ap = (const ull*)(&As[kk][tm]);
            ull a2[4] = {ap[0], ap[1], ap[2], ap[3]};
            float4 b0 = *(const float4*)(&Bs[kk][tn]);
            float4 b1 = *(const float4*)(&Bs[kk][tn + 4]);
            ull bd[8];
            bd[0]=pack2(b0.x,b0.x); bd[1]=pack2(b0.y,b0.y);
            bd[2]=pack2(b0.z,b0.z); bd[3]=pack2(b0.w,b0.w);
            bd[4]=pack2(b1.x,b1.x); bd[5]=pack2(b1.y,b1.y);
            bd[6]=pack2(b1.z,b1.z); bd[7]=pack2(b1.w,b1.w);
#pragma unroll
            for (int ip = 0; ip < 4; ip++)
#pragma unroll
                for (int j = 0; j < 8; j++)
                    acc2[ip][j] = ffma2(a2[ip], bd[j], acc2[ip][j]);
        }
        __syncthreads();
    }
    float bias[8];
#pragma unroll
    for (int j = 0; j < 8; j++) bias[j] = bx[bn + tn + j] + bh[bn + tn + j];
#pragma unroll
    for (int ip = 0; ip < 4; ip++) {
        float lo[8], hi[8];
#pragma unroll
        for (int j = 0; j < 8; j++) {
            float2 v = unpack2(acc2[ip][j]);
            lo[j] = v.x + bias[j]; hi[j] = v.y + bias[j];
        }
        float* o0 = g_xg + (size_t)(bm + tm + 2*ip)     * G4 + bn + tn;
        float* o1 = g_xg + (size_t)(bm + tm + 2*ip + 1) * G4 + bn + tn;
        *(float4*)(o0)   = make_float4(lo[0],lo[1],lo[2],lo[3]);
        *(float4*)(o0+4) = make_float4(lo[4],lo[5],lo[6],lo[7]);
        *(float4*)(o1)   = make_float4(hi[0],hi[1],hi[2],hi[3]);
        *(float4*)(o1+4) = make_float4(hi[4],hi[5],hi[6],hi[7]);
    }
}

// ---- Phase 2: persistent HMMA recurrence ----------------------------------
#define STAGE(BUF, SRCOFF) { \
    _Pragma("unroll") for (int cq = 0; cq < 8; cq++) \
        cpa(smb + (BUF) + tid * 16 + cq * 4096, hsrc + (SRCOFF) + tid * 16 + cq * 4096); \
    asm volatile("cp.async.commit_group;" ::: "memory"); }
#define WAITG(N) asm volatile("cp.async.wait_group %0;" :: "n"(N) : "memory")
#define C01(BUF, KB) \
    _Pragma("unroll") for (int j = 0; j < 32; j++) { \
        uint32_t Ah[4], Al[4], Bv[2]; \
        ldsm4(aBase + ((KB) + j) * 512, Ah); \
        ldsm4(aBase + 65536 + ((KB) + j) * 512, Al); \
        ldsm2t(bBase + (BUF) + j * 1024, Bv); \
        hmma(d, Ah, Bv); hmma(d, Al, Bv); }
#define C2(BUF, KB) \
    _Pragma("unroll") for (int j = 0; j < 32; j++) { \
        uint32_t Ah[4], Bv[2]; \
        ldsm4(aBase + ((KB) + j) * 512, Ah); \
        ldsm2t(bBase + (BUF) + j * 1024, Bv); \
        hmma(d, Ah, Bv); }

__global__ void __launch_bounds__(256, 1) lstm_hmma_kernel(float* __restrict__ out)
{
    extern __shared__ unsigned char smc[];
    const uint32_t smb = (uint32_t)__cvta_generic_to_shared(smc);
    const int tid = threadIdx.x, lane = tid & 31, w = tid >> 5;
    const int mt = w & 1, nt = w >> 1;

    // one-time: copy this block's weight image into smem (resident all steps)
    {
        const unsigned char* src = g_W + (size_t)blockIdx.x * 131072;
#pragma unroll
        for (int cq = 0; cq < 32; cq++)
            cpa(smb + tid * 16 + cq * 4096, src + tid * 16 + cq * 4096);
        asm volatile("cp.async.commit_group;" ::: "memory");
        WAITG(0);
        __syncthreads();
    }

    const int r = lane & 15, hb = lane >> 4;
    const uint32_t aBase = smb + mt * 32768 + r * 32 + ((hb ^ ((r >> 2) & 1)) << 4);
    const uint32_t bBase = smb + nt * 256 + r * 16;
    float* Dsm = (float*)(smc + DSMOFF);

    const int cell = tid & 7, b = tid >> 3;
    const int n = blockIdx.x * 8 + cell;
    float cs = 0.0f;

    for (int t = 0; t < TDIM; t++) {
        const unsigned char* hsrc = g_hB[t & 1];

        float xgv[4];
        const float* xp = g_xg + ((size_t)b * TDIM + t) * G4 + n;
#pragma unroll
        for (int g2 = 0; g2 < 4; g2++) xgv[g2] = __ldg(xp + g2 * HDIM);

        STAGE(BBUF0, 0)          // h-hi ktiles 0-31
        STAGE(BBUF1, 32768)      // h-hi ktiles 32-63
        float d[4] = {0.f, 0.f, 0.f, 0.f};
        WAITG(1); __syncthreads();
        C01(BBUF0, 0)
        __syncthreads();
        STAGE(BBUF0, 65536)      // h-lo ktiles 0-31
        WAITG(1); __syncthreads();
        C01(BBUF1, 32)
        __syncthreads();
        STAGE(BBUF1, 98304)      // h-lo ktiles 32-63
        WAITG(1); __syncthreads();
        C2(BBUF0, 0)
        __syncthreads();
        WAITG(0); __syncthreads();
        C2(BBUF1, 32)

        // fragment -> smem exchange
        {
            const int g = lane >> 2, c2 = (lane & 3) << 1;
            const int r0 = mt * 16 + g, c0 = nt * 8 + c2;
            *(float2*)(Dsm + r0 * 34 + c0)       = make_float2(d[0], d[1]);
            *(float2*)(Dsm + (r0 + 8) * 34 + c0) = make_float2(d[2], d[3]);
        }
        __syncthreads();

        // per-(cell,b) epilogue
        {
            const float gi = Dsm[cell * 34 + b]        + xgv[0];
            const float gf = Dsm[(8 + cell) * 34 + b]  + xgv[1];
            const float gg = Dsm[(16 + cell) * 34 + b] + xgv[2];
            const float go = Dsm[(24 + cell) * 34 + b] + xgv[3];
            const float si = 0.5f * (1.0f + tanhf(0.5f * gi));
            const float sf = 0.5f * (1.0f + tanhf(0.5f * gf));
            const float so = 0.5f * (1.0f + tanhf(0.5f * go));
            cs = sf * cs + si * tanhf(gg);
            const float h = so * tanhf(cs);
            out[((size_t)b * TDIM + t) * HDIM + n] = h;

            __nv_bfloat16 hh = __float2bfloat16(h);
            __nv_bfloat16 hl = __float2bfloat16(h - __bfloat162float(hh));
            unsigned char* hd = g_hB[(t + 1) & 1];
            const uint32_t off = (uint32_t)((n >> 4) * 1024 + (b >> 3) * 256
                                 + (n & 15) * 16 + (b & 7) * 2);
            *(unsigned short*)(hd + off)         = *(unsigned short*)&hh;
            *(unsigned short*)(hd + 65536 + off) = *(unsigned short*)&hl;
        }

        if (t < TDIM - 1) {
            __threadfence();
            __syncthreads();
            if (tid == 0) {
                atomicAdd(&g_count, 1);
                while (ld_acquire(&g_count) < NBLK * (t + 1)) { }
            }
            __syncthreads();
        }
    }
}

// ---------------------------------------------------------------------------
extern "C" void kernel_launch(void* const* d_in, const int* in_sizes, int n_in,
                              void* d_out, int out_size)
{
    const float* x  = (const float*)d_in[0];
    const float* Wx = (const float*)d_in[1];
    const float* bx = (const float*)d_in[2];
    const float* Wh = (const float*)d_in[3];
    const float* bh = (const float*)d_in[4];
    float* out = (float*)d_out;
    (void)in_sizes; (void)n_in; (void)out_size;

    cudaFuncSetAttribute(lstm_hmma_kernel,
                         cudaFuncAttributeMaxDynamicSharedMemorySize, SMEM_SZ);

    prep_kernel<<<8192, 256>>>(Wh);

    dim3 ggrid(G4 / 128, (32 * TDIM) / 128);
    gemm_xg_kernel<<<ggrid, 256>>>(x, Wx, bx, bh);

    lstm_hmma_kernel<<<NBLK, 256, SMEM_SZ>>>(out);
}

// round 11
// speedup vs baseline: 1.7537x; 1.2510x over previous
#include <cuda_runtime.h>
#include <cuda_bf16.h>
#include <cstdint>

#define TDIM 512
#define IDIM 512
#define HDIM 1024
#define G4   4096
#define NBLK 128
#define BBUF0 131072
#define BBUF1 163840
#define DSMOFF 196608
#define SMEM_SZ 200960

typedef unsigned long long ull;

__device__ float g_xg[(size_t)32 * TDIM * G4];
__device__ __align__(128) unsigned char g_W[(size_t)NBLK * 131072];
__device__ __align__(128) unsigned char g_hB[2][131072];
__device__ __align__(128) unsigned char g_AX[(size_t)128 * 16 * 16384]; // X hi/lo images
__device__ __align__(128) unsigned char g_BW[(size_t)32 * 16 * 16384];  // Wx hi/lo images
__device__ int g_count;

__device__ __forceinline__ int ld_acquire(const int* p) {
    int v; asm volatile("ld.global.acquire.gpu.b32 %0, [%1];" : "=r"(v) : "l"(p));
    return v;
}
__device__ __forceinline__ void ldsm4(uint32_t a, uint32_t* r) {
    asm volatile("ldmatrix.sync.aligned.m8n8.x4.shared.b16 {%0,%1,%2,%3}, [%4];"
        : "=r"(r[0]), "=r"(r[1]), "=r"(r[2]), "=r"(r[3]) : "r"(a));
}
__device__ __forceinline__ void ldsm2t(uint32_t a, uint32_t* r) {
    asm volatile("ldmatrix.sync.aligned.m8n8.x2.trans.shared.b16 {%0,%1}, [%2];"
        : "=r"(r[0]), "=r"(r[1]) : "r"(a));
}
__device__ __forceinline__ void hmma(float* d, const uint32_t* a, const uint32_t* b) {
    asm volatile("mma.sync.aligned.m16n8k16.row.col.f32.bf16.bf16.f32 "
        "{%0,%1,%2,%3},{%4,%5,%6,%7},{%8,%9},{%0,%1,%2,%3};"
        : "+f"(d[0]), "+f"(d[1]), "+f"(d[2]), "+f"(d[3])
        : "r"(a[0]), "r"(a[1]), "r"(a[2]), "r"(a[3]), "r"(b[0]), "r"(b[1]));
}
__device__ __forceinline__ void cpa(uint32_t d, const void* s) {
    asm volatile("cp.async.cg.shared.global [%0], [%1], 16;" :: "r"(d), "l"(s) : "memory");
}
__device__ __forceinline__ void split_bf16(float v, unsigned short& hi, unsigned short& lo) {
    __nv_bfloat16 h = __float2bfloat16(v);
    __nv_bfloat16 l = __float2bfloat16(v - __bfloat162float(h));
    hi = *(unsigned short*)&h; lo = *(unsigned short*)&l;
}

// ---- prep: Wh -> step-kernel A images (unchanged layout) -------------------
__global__ void __launch_bounds__(256) prep_kernel(const float* __restrict__ Wh) {
    const int e = blockIdx.x * 256 + threadIdx.x;
    const int blk = e >> 14, rem = e & 16383;
    const int m = rem >> 9, k = (rem & 511) * 2;
    const int row = ((m >> 3) << 10) + (blk << 3) + (m & 7);
    const float2 wv = *(const float2*)(Wh + (size_t)row * HDIM + k);
    unsigned short h0, l0, h1, l1;
    split_bf16(wv.x, h0, l0); split_bf16(wv.y, h1, l1);
    const int mt = m >> 4, r = m & 15, kt = k >> 4, kc = k & 15;
    const uint32_t off = (uint32_t)(mt * 32768 + kt * 512 + r * 32
                       + (((kc >> 3) ^ ((r >> 2) & 1)) << 4) + (kc & 7) * 2);
    unsigned char* base = g_W + (size_t)blk * 131072;
    *(uint32_t*)(base + off)         = (uint32_t)h0 | ((uint32_t)h1 << 16);
    *(uint32_t*)(base + 65536 + off) = (uint32_t)l0 | ((uint32_t)l1 << 16);
    if (e < 32768) ((uint32_t*)g_hB[0])[e] = 0u;
    if (e == 0) g_count = 0;
}

// ---- prep: X -> A-images for phase-1 (m-major ldsm4 tiles) ----------------
__global__ void __launch_bounds__(256) prepA_kernel(const float* __restrict__ X) {
    const int e = blockIdx.x * 256 + threadIdx.x;      // 4,194,304
    const int k = (e & 255) * 2, m = e >> 8;
    const float2 xv = *(const float2*)(X + (size_t)m * IDIM + k);
    unsigned short h0, l0, h1, l1;
    split_bf16(xv.x, h0, l0); split_bf16(xv.y, h1, l1);
    const int R = m >> 7, rr = m & 127, mm = rr >> 4, r = rr & 15;
    const int kc = k >> 5, kt = (k >> 4) & 1, kcol = k & 15;
    unsigned char* base = g_AX + (size_t)(R * 16 + kc) * 16384 + kt * 8192 + mm * 512;
    const uint32_t off = (uint32_t)(r * 32 + (((kcol >> 3) ^ ((r >> 2) & 1)) << 4)
                       + (kcol & 7) * 2);
    *(uint32_t*)(base + off)        = (uint32_t)h0 | ((uint32_t)h1 << 16);
    *(uint32_t*)(base + 4096 + off) = (uint32_t)l0 | ((uint32_t)l1 << 16);
}

// ---- prep: Wx -> B-images for phase-1 (k-major ldsm2t tiles) --------------
__global__ void __launch_bounds__(256) prepB_kernel(const float* __restrict__ Wx) {
    const int e = blockIdx.x * 256 + threadIdx.x;      // 2,097,152
    const int k = e & 511, n = e >> 9;
    const float wv = Wx[(size_t)n * IDIM + k];
    unsigned short hi, lo; split_bf16(wv, hi, lo);
    const int NB = n >> 7, cc = n & 127, nt = cc >> 3, nn = cc & 7;
    const int kc = k >> 5, kt = (k >> 4) & 1, r = k & 15;
    unsigned char* base = g_BW + (size_t)(NB * 16 + kc) * 16384 + kt * 8192 + nt * 256;
    const uint32_t off = (uint32_t)(r * 16 + nn * 2);
    *(unsigned short*)(base + off)        = hi;
    *(unsigned short*)(base + 4096 + off) = lo;
}

// ---- Phase 1: HMMA GEMM xg = X*Wx^T + (bx+bh), 3-term bf16 split ----------
__global__ void __launch_bounds__(256, 1) gemm_hmma_kernel(
    const float* __restrict__ bx, const float* __restrict__ bh)
{
    extern __shared__ unsigned char smc[];
    const uint32_t smb = (uint32_t)__cvta_generic_to_shared(smc);
    const int tid = threadIdx.x, lane = tid & 31, w = tid >> 5;
    const int mt = w & 3, nt = w >> 2;
    const int MB = blockIdx.y, NB = blockIdx.x;

    const unsigned char* srcA = g_AX + (size_t)MB * (16 * 16384);
    const unsigned char* srcB = g_BW + (size_t)NB * (16 * 16384);

    const int r = lane & 15, hb = lane >> 4;
    const uint32_t aSw = (uint32_t)(r * 32 + ((hb ^ ((r >> 2) & 1)) << 4));

    float acc[2][8][4];
#pragma unroll
    for (int i = 0; i < 2; i++)
#pragma unroll
        for (int j = 0; j < 8; j++)
#pragma unroll
            for (int q = 0; q < 4; q++) acc[i][j][q] = 0.0f;

#define LOADC(kc, s) { \
    _Pragma("unroll") for (int rd = 0; rd < 4; rd++) { \
        cpa(smb + (s) * 32768 + tid * 16 + rd * 4096, \
            srcA + (size_t)(kc) * 16384 + tid * 16 + rd * 4096); \
        cpa(smb + (s) * 32768 + 16384 + tid * 16 + rd * 4096, \
            srcB + (size_t)(kc) * 16384 + tid * 16 + rd * 4096); } \
    asm volatile("cp.async.commit_group;" ::: "memory"); }

    LOADC(0, 0)
    for (int kc = 0; kc < 16; kc++) {
        const int s = kc & 1;
        if (kc < 15) LOADC(kc + 1, 1 - s)
        if (kc < 15) { asm volatile("cp.async.wait_group 1;" ::: "memory"); }
        else         { asm volatile("cp.async.wait_group 0;" ::: "memory"); }
        __syncthreads();

#pragma unroll
        for (int kt = 0; kt < 2; kt++) {
            const uint32_t ab = smb + s * 32768 + kt * 8192;
            const uint32_t bb = smb + s * 32768 + 16384 + kt * 8192 + r * 16;
            uint32_t Ah[2][4], Al[2][4];
#pragma unroll
            for (int i = 0; i < 2; i++) {
                ldsm4(ab + (2 * mt + i) * 512 + aSw, Ah[i]);
                ldsm4(ab + 4096 + (2 * mt + i) * 512 + aSw, Al[i]);
            }
#pragma unroll
            for (int j = 0; j < 8; j++) {
                uint32_t Bh[2], Bl[2];
                ldsm2t(bb + (8 * nt + j) * 256, Bh);
                ldsm2t(bb + 4096 + (8 * nt + j) * 256, Bl);
#pragma unroll
                for (int i = 0; i < 2; i++) {
                    hmma(acc[i][j], Ah[i], Bh);
                    hmma(acc[i][j], Al[i], Bh);
                    hmma(acc[i][j], Ah[i], Bl);
                }
            }
        }
        __syncthreads();
    }

    // epilogue: bias + direct float2 stores to g_xg[m][n]
    const int g = lane >> 2, c2 = (lane & 3) << 1;
#pragma unroll
    for (int j = 0; j < 8; j++) {
        const int n0 = NB * 128 + nt * 64 + j * 8 + c2;
        const float2 bxv = *(const float2*)(bx + n0);
        const float2 bhv = *(const float2*)(bh + n0);
        const float b0 = bxv.x + bhv.x, b1 = bxv.y + bhv.y;
#pragma unroll
        for (int i = 0; i < 2; i++) {
            const int m0 = MB * 128 + mt * 32 + i * 16 + g;
            *(float2*)(g_xg + (size_t)m0 * G4 + n0) =
                make_float2(acc[i][j][0] + b0, acc[i][j][1] + b1);
            *(float2*)(g_xg + (size_t)(m0 + 8) * G4 + n0) =
                make_float2(acc[i][j][2] + b0, acc[i][j][3] + b1);
        }
    }
}

// ---- Phase 2: persistent HMMA recurrence (unchanged, proven) ---------------
#define STAGE(BUF, SRCOFF) { \
    _Pragma("unroll") for (int cq = 0; cq < 8; cq++) \
        cpa(smb + (BUF) + tid * 16 + cq * 4096, hsrc + (SRCOFF) + tid * 16 + cq * 4096); \
    asm volatile("cp.async.commit_group;" ::: "memory"); }
#define WAITG(N) asm volatile("cp.async.wait_group %0;" :: "n"(N) : "memory")
#define C01(BUF, KB) \
    _Pragma("unroll") for (int j = 0; j < 32; j++) { \
        uint32_t Ah[4], Al[4], Bv[2]; \
        ldsm4(aBase + ((KB) + j) * 512, Ah); \
        ldsm4(aBase + 65536 + ((KB) + j) * 512, Al); \
        ldsm2t(bBase + (BUF) + j * 1024, Bv); \
        hmma(d, Ah, Bv); hmma(d, Al, Bv); }
#define C2(BUF, KB) \
    _Pragma("unroll") for (int j = 0; j < 32; j++) { \
        uint32_t Ah[4], Bv[2]; \
        ldsm4(aBase + ((KB) + j) * 512, Ah); \
        ldsm2t(bBase + (BUF) + j * 1024, Bv); \
        hmma(d, Ah, Bv); }

__global__ void __launch_bounds__(256, 1) lstm_hmma_kernel(float* __restrict__ out)
{
    extern __shared__ unsigned char smc[];
    const uint32_t smb = (uint32_t)__cvta_generic_to_shared(smc);
    const int tid = threadIdx.x, lane = tid & 31, w = tid >> 5;
    const int mt = w & 1, nt = w >> 1;

    {
        const unsigned char* src = g_W + (size_t)blockIdx.x * 131072;
#pragma unroll
        for (int cq = 0; cq < 32; cq++)
            cpa(smb + tid * 16 + cq * 4096, src + tid * 16 + cq * 4096);
        asm volatile("cp.async.commit_group;" ::: "memory");
        WAITG(0);
        __syncthreads();
    }

    const int r = lane & 15, hb = lane >> 4;
    const uint32_t aBase = smb + mt * 32768 + r * 32 + ((hb ^ ((r >> 2) & 1)) << 4);
    const uint32_t bBase = smb + nt * 256 + r * 16;
    float* Dsm = (float*)(smc + DSMOFF);

    const int cell = tid & 7, b = tid >> 3;
    const int n = blockIdx.x * 8 + cell;
    float cs = 0.0f;

    for (int t = 0; t < TDIM; t++) {
        const unsigned char* hsrc = g_hB[t & 1];

        float xgv[4];
        const float* xp = g_xg + ((size_t)b * TDIM + t) * G4 + n;
#pragma unroll
        for (int g2 = 0; g2 < 4; g2++) xgv[g2] = __ldg(xp + g2 * HDIM);

        STAGE(BBUF0, 0)
        STAGE(BBUF1, 32768)
        float d[4] = {0.f, 0.f, 0.f, 0.f};
        WAITG(1); __syncthreads();
        C01(BBUF0, 0)
        __syncthreads();
        STAGE(BBUF0, 65536)
        WAITG(1); __syncthreads();
        C01(BBUF1, 32)
        __syncthreads();
        STAGE(BBUF1, 98304)
        WAITG(1); __syncthreads();
        C2(BBUF0, 0)
        __syncthreads();
        WAITG(0); __syncthreads();
        C2(BBUF1, 32)

        {
            const int g = lane >> 2, c2 = (lane & 3) << 1;
            const int r0 = mt * 16 + g, c0 = nt * 8 + c2;
            *(float2*)(Dsm + r0 * 34 + c0)       = make_float2(d[0], d[1]);
            *(float2*)(Dsm + (r0 + 8) * 34 + c0) = make_float2(d[2], d[3]);
        }
        __syncthreads();

        {
            const float gi = Dsm[cell * 34 + b]        + xgv[0];
            const float gf = Dsm[(8 + cell) * 34 + b]  + xgv[1];
            const float gg = Dsm[(16 + cell) * 34 + b] + xgv[2];
            const float go = Dsm[(24 + cell) * 34 + b] + xgv[3];
            const float si = 0.5f * (1.0f + tanhf(0.5f * gi));
            const float sf = 0.5f * (1.0f + tanhf(0.5f * gf));
            const float so = 0.5f * (1.0f + tanhf(0.5f * go));
            cs = sf * cs + si * tanhf(gg);
            const float h = so * tanhf(cs);
            out[((size_t)b * TDIM + t) * HDIM + n] = h;

            unsigned short hh, hl; split_bf16(h, hh, hl);
            unsigned char* hd = g_hB[(t + 1) & 1];
            const uint32_t off = (uint32_t)((n >> 4) * 1024 + (b >> 3) * 256
                                 + (n & 15) * 16 + (b & 7) * 2);
            *(unsigned short*)(hd + off)         = hh;
            *(unsigned short*)(hd + 65536 + off) = hl;
        }

        if (t < TDIM - 1) {
            __threadfence();
            __syncthreads();
            if (tid == 0) {
                atomicAdd(&g_count, 1);
                while (ld_acquire(&g_count) < NBLK * (t + 1)) { }
            }
            __syncthreads();
        }
    }
}

// ---------------------------------------------------------------------------
extern "C" void kernel_launch(void* const* d_in, const int* in_sizes, int n_in,
                              void* d_out, int out_size)
{
    const float* x  = (const float*)d_in[0];
    const float* Wx = (const float*)d_in[1];
    const float* bx = (const float*)d_in[2];
    const float* Wh = (const float*)d_in[3];
    const float* bh = (const float*)d_in[4];
    float* out = (float*)d_out;
    (void)in_sizes; (void)n_in; (void)out_size;

    cudaFuncSetAttribute(lstm_hmma_kernel,
                         cudaFuncAttributeMaxDynamicSharedMemorySize, SMEM_SZ);
    cudaFuncSetAttribute(gemm_hmma_kernel,
                         cudaFuncAttributeMaxDynamicSharedMemorySize, 65536);

    prep_kernel<<<8192, 256>>>(Wh);
    prepA_kernel<<<16384, 256>>>(x);
    prepB_kernel<<<8192, 256>>>(Wx);

    dim3 ggrid(32, 128);
    gemm_hmma_kernel<<<ggrid, 256, 65536>>>(bx, bh);

    lstm_hmma_kernel<<<NBLK, 256, SMEM_SZ>>>(out);
}

// round 12
// speedup vs baseline: 2.3854x; 1.3602x over previous
#include <cuda_runtime.h>
#include <cuda_bf16.h>
#include <cstdint>

#define TDIM 512
#define IDIM 512
#define HDIM 1024
#define G4   4096
#define NBLK 128
#define HBH  0
#define HBL  65536
#define DPOFF 131072
#define SMEM2 165888            // 131072 B-buffers + 8*1088*4 partials
#define SMEM_G 65536

typedef unsigned long long ull;

__device__ float g_xg[(size_t)32 * TDIM * G4];
__device__ __align__(128) unsigned char g_W[(size_t)NBLK * 131072];
__device__ __align__(128) unsigned char g_hB[2][131072];
__device__ __align__(128) unsigned char g_AX[(size_t)128 * 16 * 16384];
__device__ __align__(128) unsigned char g_BW[(size_t)32 * 16 * 16384];
__device__ int g_count;

__device__ __forceinline__ int ld_acquire(const int* p) {
    int v; asm volatile("ld.global.acquire.gpu.b32 %0, [%1];" : "=r"(v) : "l"(p));
    return v;
}
__device__ __forceinline__ void ldsm4(uint32_t a, uint32_t* r) {
    asm volatile("ldmatrix.sync.aligned.m8n8.x4.shared.b16 {%0,%1,%2,%3}, [%4];"
        : "=r"(r[0]), "=r"(r[1]), "=r"(r[2]), "=r"(r[3]) : "r"(a));
}
__device__ __forceinline__ void ldsm2t(uint32_t a, uint32_t* r) {
    asm volatile("ldmatrix.sync.aligned.m8n8.x2.trans.shared.b16 {%0,%1}, [%2];"
        : "=r"(r[0]), "=r"(r[1]) : "r"(a));
}
__device__ __forceinline__ void hmma(float* d, const uint32_t* a, const uint32_t* b) {
    asm volatile("mma.sync.aligned.m16n8k16.row.col.f32.bf16.bf16.f32 "
        "{%0,%1,%2,%3},{%4,%5,%6,%7},{%8,%9},{%0,%1,%2,%3};"
        : "+f"(d[0]), "+f"(d[1]), "+f"(d[2]), "+f"(d[3])
        : "r"(a[0]), "r"(a[1]), "r"(a[2]), "r"(a[3]), "r"(b[0]), "r"(b[1]));
}
__device__ __forceinline__ void cpa(uint32_t d, const void* s) {
    asm volatile("cp.async.cg.shared.global [%0], [%1], 16;" :: "r"(d), "l"(s) : "memory");
}
#define WAITG(N) asm volatile("cp.async.wait_group %0;" :: "n"(N) : "memory")
__device__ __forceinline__ void split_bf16(float v, unsigned short& hi, unsigned short& lo) {
    __nv_bfloat16 h = __float2bfloat16(v);
    __nv_bfloat16 l = __float2bfloat16(v - __bfloat162float(h));
    hi = *(unsigned short*)&h; lo = *(unsigned short*)&l;
}

// ---- prep: Wh -> step-kernel A images --------------------------------------
__global__ void __launch_bounds__(256) prep_kernel(const float* __restrict__ Wh) {
    const int e = blockIdx.x * 256 + threadIdx.x;
    const int blk = e >> 14, rem = e & 16383;
    const int m = rem >> 9, k = (rem & 511) * 2;
    const int row = ((m >> 3) << 10) + (blk << 3) + (m & 7);
    const float2 wv = *(const float2*)(Wh + (size_t)row * HDIM + k);
    unsigned short h0, l0, h1, l1;
    split_bf16(wv.x, h0, l0); split_bf16(wv.y, h1, l1);
    const int mt = m >> 4, r = m & 15, kt = k >> 4, kc = k & 15;
    const uint32_t off = (uint32_t)(mt * 32768 + kt * 512 + r * 32
                       + (((kc >> 3) ^ ((r >> 2) & 1)) << 4) + (kc & 7) * 2);
    unsigned char* base = g_W + (size_t)blk * 131072;
    *(uint32_t*)(base + off)         = (uint32_t)h0 | ((uint32_t)h1 << 16);
    *(uint32_t*)(base + 65536 + off) = (uint32_t)l0 | ((uint32_t)l1 << 16);
    if (e < 32768) ((uint32_t*)g_hB[0])[e] = 0u;
    if (e == 0) g_count = 0;
}

// ---- prep: X -> phase-1 A-images -------------------------------------------
__global__ void __launch_bounds__(256) prepA_kernel(const float* __restrict__ X) {
    const int e = blockIdx.x * 256 + threadIdx.x;
    const int k = (e & 255) * 2, m = e >> 8;
    const float2 xv = *(const float2*)(X + (size_t)m * IDIM + k);
    unsigned short h0, l0, h1, l1;
    split_bf16(xv.x, h0, l0); split_bf16(xv.y, h1, l1);
    const int R = m >> 7, rr = m & 127, mm = rr >> 4, r = rr & 15;
    const int kc = k >> 5, kt = (k >> 4) & 1, kcol = k & 15;
    unsigned char* base = g_AX + (size_t)(R * 16 + kc) * 16384 + kt * 8192 + mm * 512;
    const uint32_t off = (uint32_t)(r * 32 + (((kcol >> 3) ^ ((r >> 2) & 1)) << 4)
                       + (kcol & 7) * 2);
    *(uint32_t*)(base + off)        = (uint32_t)h0 | ((uint32_t)h1 << 16);
    *(uint32_t*)(base + 4096 + off) = (uint32_t)l0 | ((uint32_t)l1 << 16);
}

// ---- prep: Wx -> phase-1 B-images ------------------------------------------
__global__ void __launch_bounds__(256) prepB_kernel(const float* __restrict__ Wx) {
    const int e = blockIdx.x * 256 + threadIdx.x;
    const int k = e & 511, n = e >> 9;
    const float wv = Wx[(size_t)n * IDIM + k];
    unsigned short hi, lo; split_bf16(wv, hi, lo);
    const int NB = n >> 7, cc = n & 127, nt = cc >> 3, nn = cc & 7;
    const int kc = k >> 5, kt = (k >> 4) & 1, r = k & 15;
    unsigned char* base = g_BW + (size_t)(NB * 16 + kc) * 16384 + kt * 8192 + nt * 256;
    const uint32_t off = (uint32_t)(r * 16 + nn * 2);
    *(unsigned short*)(base + off)        = hi;
    *(unsigned short*)(base + 4096 + off) = lo;
}

// ---- Phase 1: HMMA GEMM (proven, unchanged) --------------------------------
__global__ void __launch_bounds__(256, 1) gemm_hmma_kernel(
    const float* __restrict__ bx, const float* __restrict__ bh)
{
    extern __shared__ unsigned char smc[];
    const uint32_t smb = (uint32_t)__cvta_generic_to_shared(smc);
    const int tid = threadIdx.x, lane = tid & 31, w = tid >> 5;
    const int mt = w & 3, nt = w >> 2;
    const int MB = blockIdx.y, NB = blockIdx.x;
    const unsigned char* srcA = g_AX + (size_t)MB * (16 * 16384);
    const unsigned char* srcB = g_BW + (size_t)NB * (16 * 16384);
    const int r = lane & 15, hb = lane >> 4;
    const uint32_t aSw = (uint32_t)(r * 32 + ((hb ^ ((r >> 2) & 1)) << 4));

    float acc[2][8][4];
#pragma unroll
    for (int i = 0; i < 2; i++)
#pragma unroll
        for (int j = 0; j < 8; j++)
#pragma unroll
            for (int q = 0; q < 4; q++) acc[i][j][q] = 0.0f;

#define LOADC(kc, s) { \
    _Pragma("unroll") for (int rd = 0; rd < 4; rd++) { \
        cpa(smb + (s) * 32768 + tid * 16 + rd * 4096, \
            srcA + (size_t)(kc) * 16384 + tid * 16 + rd * 4096); \
        cpa(smb + (s) * 32768 + 16384 + tid * 16 + rd * 4096, \
            srcB + (size_t)(kc) * 16384 + tid * 16 + rd * 4096); } \
    asm volatile("cp.async.commit_group;" ::: "memory"); }

    LOADC(0, 0)
    for (int kc = 0; kc < 16; kc++) {
        const int s = kc & 1;
        if (kc < 15) LOADC(kc + 1, 1 - s)
        if (kc < 15) { WAITG(1); } else { WAITG(0); }
        __syncthreads();
#pragma unroll
        for (int kt = 0; kt < 2; kt++) {
            const uint32_t ab = smb + s * 32768 + kt * 8192;
            const uint32_t bb = smb + s * 32768 + 16384 + kt * 8192 + r * 16;
            uint32_t Ah[2][4], Al[2][4];
#pragma unroll
            for (int i = 0; i < 2; i++) {
                ldsm4(ab + (2 * mt + i) * 512 + aSw, Ah[i]);
                ldsm4(ab + 4096 + (2 * mt + i) * 512 + aSw, Al[i]);
            }
#pragma unroll
            for (int j = 0; j < 8; j++) {
                uint32_t Bh[2], Bl[2];
                ldsm2t(bb + (8 * nt + j) * 256, Bh);
                ldsm2t(bb + 4096 + (8 * nt + j) * 256, Bl);
#pragma unroll
                for (int i = 0; i < 2; i++) {
                    hmma(acc[i][j], Ah[i], Bh);
                    hmma(acc[i][j], Al[i], Bh);
                    hmma(acc[i][j], Ah[i], Bl);
                }
            }
        }
        __syncthreads();
    }
    const int g = lane >> 2, c2 = (lane & 3) << 1;
#pragma unroll
    for (int j = 0; j < 8; j++) {
        const int n0 = NB * 128 + nt * 64 + j * 8 + c2;
        const float2 bxv = *(const float2*)(bx + n0);
        const float2 bhv = *(const float2*)(bh + n0);
        const float b0 = bxv.x + bhv.x, b1 = bxv.y + bhv.y;
#pragma unroll
        for (int i = 0; i < 2; i++) {
            const int m0 = MB * 128 + mt * 32 + i * 16 + g;
            *(float2*)(g_xg + (size_t)m0 * G4 + n0) =
                make_float2(acc[i][j][0] + b0, acc[i][j][1] + b1);
            *(float2*)(g_xg + (size_t)(m0 + 8) * G4 + n0) =
                make_float2(acc[i][j][2] + b0, acc[i][j][3] + b1);
        }
    }
}

// ---- Phase 2: persistent HMMA recurrence, A in registers, K-sliced warps ---
__global__ void __launch_bounds__(256, 1) lstm_hmma_kernel(float* __restrict__ out)
{
    extern __shared__ unsigned char smc[];
    const uint32_t smb = (uint32_t)__cvta_generic_to_shared(smc);
    const int tid = threadIdx.x, lane = tid & 31, w = tid >> 5;
    const int r = lane & 15, hb = lane >> 4;

    // one-time: stage weight image, load this warp's K-slice A frags to regs
    {
        const unsigned char* src = g_W + (size_t)blockIdx.x * 131072;
#pragma unroll
        for (int cq = 0; cq < 32; cq++)
            cpa(smb + tid * 16 + cq * 4096, src + tid * 16 + cq * 4096);
        asm volatile("cp.async.commit_group;" ::: "memory");
        WAITG(0);
        __syncthreads();
    }
    uint32_t Ah[2][8][4], Al[2][8][4];
    {
        const uint32_t aSw = (uint32_t)(r * 32 + ((hb ^ ((r >> 2) & 1)) << 4));
#pragma unroll
        for (int mt = 0; mt < 2; mt++)
#pragma unroll
            for (int j = 0; j < 8; j++) {
                ldsm4(smb + mt * 32768 + (w * 8 + j) * 512 + aSw, Ah[mt][j]);
                ldsm4(smb + 65536 + mt * 32768 + (w * 8 + j) * 512 + aSw, Al[mt][j]);
            }
    }
    __syncthreads();   // weight smem now dead -> reused as B buffers

    float* Dp = (float*)(smc + DPOFF);
    const int cell = tid & 7, b = tid >> 3;
    const int n = blockIdx.x * 8 + cell;
    float cs = 0.0f;

    for (int t = 0; t < TDIM; t++) {
        const unsigned char* hsrc = g_hB[t & 1];
        // stage h-hi (group1), h-lo (group0)
#pragma unroll
        for (int cq = 0; cq < 16; cq++)
            cpa(smb + HBH + tid * 16 + cq * 4096, hsrc + tid * 16 + cq * 4096);
        asm volatile("cp.async.commit_group;" ::: "memory");
#pragma unroll
        for (int cq = 0; cq < 16; cq++)
            cpa(smb + HBL + tid * 16 + cq * 4096, hsrc + 65536 + tid * 16 + cq * 4096);
        asm volatile("cp.async.commit_group;" ::: "memory");

        float xgv[4];
        const float* xp = g_xg + ((size_t)b * TDIM + t) * G4 + n;
#pragma unroll
        for (int g2 = 0; g2 < 4; g2++) xgv[g2] = __ldg(xp + g2 * HDIM);

        float acc[2][4][4];
#pragma unroll
        for (int mt = 0; mt < 2; mt++)
#pragma unroll
            for (int nt = 0; nt < 4; nt++)
#pragma unroll
                for (int q = 0; q < 4; q++) acc[mt][nt][q] = 0.0f;

        WAITG(1); __syncthreads();
#pragma unroll
        for (int j = 0; j < 8; j++)
#pragma unroll
            for (int nt = 0; nt < 4; nt++) {
                uint32_t Bh[2];
                ldsm2t(smb + HBH + (w * 8 + j) * 1024 + nt * 256 + r * 16, Bh);
                hmma(acc[0][nt], Ah[0][j], Bh);
                hmma(acc[1][nt], Ah[1][j], Bh);
                hmma(acc[0][nt], Al[0][j], Bh);
                hmma(acc[1][nt], Al[1][j], Bh);
            }
        WAITG(0); __syncthreads();
#pragma unroll
        for (int j = 0; j < 8; j++)
#pragma unroll
            for (int nt = 0; nt < 4; nt++) {
                uint32_t Bl[2];
                ldsm2t(smb + HBL + (w * 8 + j) * 1024 + nt * 256 + r * 16, Bl);
                hmma(acc[0][nt], Ah[0][j], Bl);
                hmma(acc[1][nt], Ah[1][j], Bl);
            }

        // store K-partials: Dp[w][m][b], pad 34
        {
            const int g = lane >> 2, c2 = (lane & 3) << 1;
            float* dpw = Dp + w * 1088;
#pragma unroll
            for (int mt = 0; mt < 2; mt++)
#pragma unroll
                for (int nt = 0; nt < 4; nt++) {
                    const int r0 = mt * 16 + g, c0 = nt * 8 + c2;
                    *(float2*)(dpw + r0 * 34 + c0) =
                        make_float2(acc[mt][nt][0], acc[mt][nt][1]);
                    *(float2*)(dpw + (r0 + 8) * 34 + c0) =
                        make_float2(acc[mt][nt][2], acc[mt][nt][3]);
                }
        }
        __syncthreads();

        // epilogue: thread (cell,b) reduces 8 partials x 4 gates
        {
            float s0 = xgv[0], s1 = xgv[1], s2 = xgv[2], s3 = xgv[3];
#pragma unroll
            for (int w2 = 0; w2 < 8; w2++) {
                const float* dpw = Dp + w2 * 1088 + cell * 34 + b;
                s0 += dpw[0];
                s1 += dpw[8 * 34];
                s2 += dpw[16 * 34];
                s3 += dpw[24 * 34];
            }
            const float si = 0.5f * (1.0f + tanhf(0.5f * s0));
            const float sf = 0.5f * (1.0f + tanhf(0.5f * s1));
            const float so = 0.5f * (1.0f + tanhf(0.5f * s3));
            cs = sf * cs + si * tanhf(s2);
            const float h = so * tanhf(cs);
            out[((size_t)b * TDIM + t) * HDIM + n] = h;

            unsigned short hh, hl; split_bf16(h, hh, hl);
            unsigned char* hd = g_hB[(t + 1) & 1];
            const uint32_t off = (uint32_t)((n >> 4) * 1024 + (b >> 3) * 256
                                 + (n & 15) * 16 + (b & 7) * 2);
            *(unsigned short*)(hd + off)         = hh;
            *(unsigned short*)(hd + 65536 + off) = hl;
        }

        if (t < TDIM - 1) {
            __threadfence();
            __syncthreads();
            if (tid == 0) {
                atomicAdd(&g_count, 1);
                while (ld_acquire(&g_count) < NBLK * (t + 1)) { }
            }
            __syncthreads();
        }
    }
}

// ---------------------------------------------------------------------------
extern "C" void kernel_launch(void* const* d_in, const int* in_sizes, int n_in,
                              void* d_out, int out_size)
{
    const float* x  = (const float*)d_in[0];
    const float* Wx = (const float*)d_in[1];
    const float* bx = (const float*)d_in[2];
    const float* Wh = (const float*)d_in[3];
    const float* bh = (const float*)d_in[4];
    float* out = (float*)d_out;
    (void)in_sizes; (void)n_in; (void)out_size;

    cudaFuncSetAttribute(lstm_hmma_kernel,
                         cudaFuncAttributeMaxDynamicSharedMemorySize, SMEM2);
    cudaFuncSetAttribute(gemm_hmma_kernel,
                         cudaFuncAttributeMaxDynamicSharedMemorySize, SMEM_G);

    prep_kernel<<<8192, 256>>>(Wh);
    prepA_kernel<<<16384, 256>>>(x);
    prepB_kernel<<<8192, 256>>>(Wx);

    dim3 ggrid(32, 128);
    gemm_hmma_kernel<<<ggrid, 256, SMEM_G>>>(bx, bh);

    lstm_hmma_kernel<<<NBLK, 256, SMEM2>>>(out);
}

// round 13
// speedup vs baseline: 2.4752x; 1.0376x over previous
#include <cuda_runtime.h>
#include <cuda_bf16.h>
#include <cstdint>

#define TDIM 512
#define IDIM 512
#define HDIM 1024
#define G4   4096
#define NBLK 128
#define HBH  0
#define HBL  65536
#define DPOFF 131072
#define SMEM2 165888
#define SMEM_G 65536

typedef unsigned long long ull;

__device__ float g_xg[(size_t)32 * TDIM * G4];
__device__ __align__(128) unsigned char g_W[(size_t)NBLK * 131072];
__device__ __align__(128) unsigned char g_hB[2][131072];
__device__ __align__(128) unsigned char g_AX[(size_t)128 * 16 * 16384];
__device__ __align__(128) unsigned char g_BW[(size_t)32 * 16 * 16384];
__device__ int g_count;

__device__ __forceinline__ int ld_acquire(const int* p) {
    int v; asm volatile("ld.global.acquire.gpu.b32 %0, [%1];" : "=r"(v) : "l"(p));
    return v;
}
__device__ __forceinline__ void ldsm4(uint32_t a, uint32_t* r) {
    asm volatile("ldmatrix.sync.aligned.m8n8.x4.shared.b16 {%0,%1,%2,%3}, [%4];"
        : "=r"(r[0]), "=r"(r[1]), "=r"(r[2]), "=r"(r[3]) : "r"(a));
}
__device__ __forceinline__ void ldsm4t(uint32_t a, uint32_t* r) {
    asm volatile("ldmatrix.sync.aligned.m8n8.x4.trans.shared.b16 {%0,%1,%2,%3}, [%4];"
        : "=r"(r[0]), "=r"(r[1]), "=r"(r[2]), "=r"(r[3]) : "r"(a));
}
__device__ __forceinline__ void hmma(float* d, const uint32_t* a, const uint32_t* b) {
    asm volatile("mma.sync.aligned.m16n8k16.row.col.f32.bf16.bf16.f32 "
        "{%0,%1,%2,%3},{%4,%5,%6,%7},{%8,%9},{%0,%1,%2,%3};"
        : "+f"(d[0]), "+f"(d[1]), "+f"(d[2]), "+f"(d[3])
        : "r"(a[0]), "r"(a[1]), "r"(a[2]), "r"(a[3]), "r"(b[0]), "r"(b[1]));
}
__device__ __forceinline__ void cpa(uint32_t d, const void* s) {
    asm volatile("cp.async.cg.shared.global [%0], [%1], 16;" :: "r"(d), "l"(s) : "memory");
}
#define WAITG(N) asm volatile("cp.async.wait_group %0;" :: "n"(N) : "memory")
__device__ __forceinline__ void split_bf16(float v, unsigned short& hi, unsigned short& lo) {
    __nv_bfloat16 h = __float2bfloat16(v);
    __nv_bfloat16 l = __float2bfloat16(v - __bfloat162float(h));
    hi = *(unsigned short*)&h; lo = *(unsigned short*)&l;
}

// ---- prep: Wh -> step-kernel A images --------------------------------------
__global__ void __launch_bounds__(256) prep_kernel(const float* __restrict__ Wh) {
    const int e = blockIdx.x * 256 + threadIdx.x;
    const int blk = e >> 14, rem = e & 16383;
    const int m = rem >> 9, k = (rem & 511) * 2;
    const int row = ((m >> 3) << 10) + (blk << 3) + (m & 7);
    const float2 wv = *(const float2*)(Wh + (size_t)row * HDIM + k);
    unsigned short h0, l0, h1, l1;
    split_bf16(wv.x, h0, l0); split_bf16(wv.y, h1, l1);
    const int mt = m >> 4, r = m & 15, kt = k >> 4, kc = k & 15;
    const uint32_t off = (uint32_t)(mt * 32768 + kt * 512 + r * 32
                       + (((kc >> 3) ^ ((r >> 2) & 1)) << 4) + (kc & 7) * 2);
    unsigned char* base = g_W + (size_t)blk * 131072;
    *(uint32_t*)(base + off)         = (uint32_t)h0 | ((uint32_t)h1 << 16);
    *(uint32_t*)(base + 65536 + off) = (uint32_t)l0 | ((uint32_t)l1 << 16);
    if (e < 32768) ((uint32_t*)g_hB[0])[e] = 0u;
    if (e == 0) g_count = 0;
}

// ---- prep: X -> phase-1 A-images -------------------------------------------
__global__ void __launch_bounds__(256) prepA_kernel(const float* __restrict__ X) {
    const int e = blockIdx.x * 256 + threadIdx.x;
    const int k = (e & 255) * 2, m = e >> 8;
    const float2 xv = *(const float2*)(X + (size_t)m * IDIM + k);
    unsigned short h0, l0, h1, l1;
    split_bf16(xv.x, h0, l0); split_bf16(xv.y, h1, l1);
    const int R = m >> 7, rr = m & 127, mm = rr >> 4, r = rr & 15;
    const int kc = k >> 5, kt = (k >> 4) & 1, kcol = k & 15;
    unsigned char* base = g_AX + (size_t)(R * 16 + kc) * 16384 + kt * 8192 + mm * 512;
    const uint32_t off = (uint32_t)(r * 32 + (((kcol >> 3) ^ ((r >> 2) & 1)) << 4)
                       + (kcol & 7) * 2);
    *(uint32_t*)(base + off)        = (uint32_t)h0 | ((uint32_t)h1 << 16);
    *(uint32_t*)(base + 4096 + off) = (uint32_t)l0 | ((uint32_t)l1 << 16);
}

// ---- prep: Wx -> phase-1 B-images ------------------------------------------
__global__ void __launch_bounds__(256) prepB_kernel(const float* __restrict__ Wx) {
    const int e = blockIdx.x * 256 + threadIdx.x;
    const int k = e & 511, n = e >> 9;
    const float wv = Wx[(size_t)n * IDIM + k];
    unsigned short hi, lo; split_bf16(wv, hi, lo);
    const int NB = n >> 7, cc = n & 127, nt = cc >> 3, nn = cc & 7;
    const int kc = k >> 5, kt = (k >> 4) & 1, r = k & 15;
    unsigned char* base = g_BW + (size_t)(NB * 16 + kc) * 16384 + kt * 8192 + nt * 256;
    const uint32_t off = (uint32_t)(r * 16 + nn * 2);
    *(unsigned short*)(base + off)        = hi;
    *(unsigned short*)(base + 4096 + off) = lo;
}

// ---- Phase 1: HMMA GEMM, x4-trans B loads ----------------------------------
__global__ void __launch_bounds__(256, 1) gemm_hmma_kernel(
    const float* __restrict__ bx, const float* __restrict__ bh)
{
    extern __shared__ unsigned char smc[];
    const uint32_t smb = (uint32_t)__cvta_generic_to_shared(smc);
    const int tid = threadIdx.x, lane = tid & 31, w = tid >> 5;
    const int mt = w & 3, nt = w >> 2;
    const int MB = blockIdx.y, NB = blockIdx.x;
    const unsigned char* srcA = g_AX + (size_t)MB * (16 * 16384);
    const unsigned char* srcB = g_BW + (size_t)NB * (16 * 16384);
    const int r = lane & 15, hb = lane >> 4;
    const uint32_t aSw = (uint32_t)(r * 32 + ((hb ^ ((r >> 2) & 1)) << 4));
    const uint32_t tb  = (uint32_t)(r * 16 + hb * 256);   // x4-trans lane addr

    float acc[2][8][4];
#pragma unroll
    for (int i = 0; i < 2; i++)
#pragma unroll
        for (int j = 0; j < 8; j++)
#pragma unroll
            for (int q = 0; q < 4; q++) acc[i][j][q] = 0.0f;

#define LOADC(kc, s) { \
    _Pragma("unroll") for (int rd = 0; rd < 4; rd++) { \
        cpa(smb + (s) * 32768 + tid * 16 + rd * 4096, \
            srcA + (size_t)(kc) * 16384 + tid * 16 + rd * 4096); \
        cpa(smb + (s) * 32768 + 16384 + tid * 16 + rd * 4096, \
            srcB + (size_t)(kc) * 16384 + tid * 16 + rd * 4096); } \
    asm volatile("cp.async.commit_group;" ::: "memory"); }

    LOADC(0, 0)
    for (int kc = 0; kc < 16; kc++) {
        const int s = kc & 1;
        if (kc < 15) LOADC(kc + 1, 1 - s)
        if (kc < 15) { WAITG(1); } else { WAITG(0); }
        __syncthreads();
#pragma unroll
        for (int kt = 0; kt < 2; kt++) {
            const uint32_t ab = smb + s * 32768 + kt * 8192;
            const uint32_t bb = smb + s * 32768 + 16384 + kt * 8192 + tb;
            uint32_t Ah[2][4], Al[2][4];
#pragma unroll
            for (int i = 0; i < 2; i++) {
                ldsm4(ab + (2 * mt + i) * 512 + aSw, Ah[i]);
                ldsm4(ab + 4096 + (2 * mt + i) * 512 + aSw, Al[i]);
            }
#pragma unroll
            for (int jj = 0; jj < 4; jj++) {
                uint32_t Bh4[4], Bl4[4];
                ldsm4t(bb + (8 * nt + 2 * jj) * 256, Bh4);
                ldsm4t(bb + 4096 + (8 * nt + 2 * jj) * 256, Bl4);
#pragma unroll
                for (int sj = 0; sj < 2; sj++) {
                    const uint32_t* Bh = Bh4 + 2 * sj;
                    const uint32_t* Bl = Bl4 + 2 * sj;
#pragma unroll
                    for (int i = 0; i < 2; i++) {
                        hmma(acc[i][2 * jj + sj], Ah[i], Bh);
                        hmma(acc[i][2 * jj + sj], Al[i], Bh);
                        hmma(acc[i][2 * jj + sj], Ah[i], Bl);
                    }
                }
            }
        }
        __syncthreads();
    }
    const int g = lane >> 2, c2 = (lane & 3) << 1;
#pragma unroll
    for (int j = 0; j < 8; j++) {
        const int n0 = NB * 128 + nt * 64 + j * 8 + c2;
        const float2 bxv = *(const float2*)(bx + n0);
        const float2 bhv = *(const float2*)(bh + n0);
        const float b0 = bxv.x + bhv.x, b1 = bxv.y + bhv.y;
#pragma unroll
        for (int i = 0; i < 2; i++) {
            const int m0 = MB * 128 + mt * 32 + i * 16 + g;
            *(float2*)(g_xg + (size_t)m0 * G4 + n0) =
                make_float2(acc[i][j][0] + b0, acc[i][j][1] + b1);
            *(float2*)(g_xg + (size_t)(m0 + 8) * G4 + n0) =
                make_float2(acc[i][j][2] + b0, acc[i][j][3] + b1);
        }
    }
}

// ---- Phase 2: persistent HMMA recurrence, per-warp B staging ---------------
__global__ void __launch_bounds__(256, 1) lstm_hmma_kernel(float* __restrict__ out)
{
    extern __shared__ unsigned char smc[];
    const uint32_t smb = (uint32_t)__cvta_generic_to_shared(smc);
    const int tid = threadIdx.x, lane = tid & 31, w = tid >> 5;
    const int r = lane & 15, hb = lane >> 4;

    // one-time: stage weight image, load this warp's K-slice A frags to regs
    {
        const unsigned char* src = g_W + (size_t)blockIdx.x * 131072;
#pragma unroll
        for (int cq = 0; cq < 32; cq++)
            cpa(smb + tid * 16 + cq * 4096, src + tid * 16 + cq * 4096);
        asm volatile("cp.async.commit_group;" ::: "memory");
        WAITG(0);
        __syncthreads();
    }
    uint32_t Ah[2][8][4], Al[2][8][4];
    {
        const uint32_t aSw = (uint32_t)(r * 32 + ((hb ^ ((r >> 2) & 1)) << 4));
#pragma unroll
        for (int mt = 0; mt < 2; mt++)
#pragma unroll
            for (int j = 0; j < 8; j++) {
                ldsm4(smb + mt * 32768 + (w * 8 + j) * 512 + aSw, Ah[mt][j]);
                ldsm4(smb + 65536 + mt * 32768 + (w * 8 + j) * 512 + aSw, Al[mt][j]);
            }
    }
    __syncthreads();   // weight smem now dead -> reused as B buffers

    float* Dp = (float*)(smc + DPOFF);
    const int cell = tid & 7, b = tid >> 3;
    const int n = blockIdx.x * 8 + cell;
    const uint32_t tb = (uint32_t)(r * 16 + hb * 256);   // x4-trans lane addr
    float cs = 0.0f;

    for (int t = 0; t < TDIM; t++) {
        const unsigned char* hsrc = g_hB[t & 1];
        // per-warp staging: warp w needs only its 8KB hi + 8KB lo K-slice
        {
            const uint32_t dh = smb + HBH + w * 8192 + lane * 16;
            const uint32_t dl = smb + HBL + w * 8192 + lane * 16;
            const unsigned char* sh = hsrc + w * 8192 + lane * 16;
            const unsigned char* sl = hsrc + 65536 + w * 8192 + lane * 16;
#pragma unroll
            for (int q = 0; q < 16; q++) cpa(dh + q * 512, sh + q * 512);
            asm volatile("cp.async.commit_group;" ::: "memory");
#pragma unroll
            for (int q = 0; q < 16; q++) cpa(dl + q * 512, sl + q * 512);
            asm volatile("cp.async.commit_group;" ::: "memory");
        }

        float xgv[4];
        const float* xp = g_xg + ((size_t)b * TDIM + t) * G4 + n;
#pragma unroll
        for (int g2 = 0; g2 < 4; g2++) xgv[g2] = __ldg(xp + g2 * HDIM);

        float acc[2][4][4];
#pragma unroll
        for (int mt = 0; mt < 2; mt++)
#pragma unroll
            for (int nt = 0; nt < 4; nt++)
#pragma unroll
                for (int q = 0; q < 4; q++) acc[mt][nt][q] = 0.0f;

        WAITG(1); __syncwarp();
#pragma unroll
        for (int j = 0; j < 8; j++) {
            uint32_t B01[4], B23[4];
            const uint32_t jb = smb + HBH + (w * 8 + j) * 1024 + tb;
            ldsm4t(jb, B01);
            ldsm4t(jb + 512, B23);
#pragma unroll
            for (int mt = 0; mt < 2; mt++) {
                hmma(acc[mt][0], Ah[mt][j], B01);
                hmma(acc[mt][1], Ah[mt][j], B01 + 2);
                hmma(acc[mt][2], Ah[mt][j], B23);
                hmma(acc[mt][3], Ah[mt][j], B23 + 2);
                hmma(acc[mt][0], Al[mt][j], B01);
                hmma(acc[mt][1], Al[mt][j], B01 + 2);
                hmma(acc[mt][2], Al[mt][j], B23);
                hmma(acc[mt][3], Al[mt][j], B23 + 2);
            }
        }
        WAITG(0); __syncwarp();
#pragma unroll
        for (int j = 0; j < 8; j++) {
            uint32_t B01[4], B23[4];
            const uint32_t jb = smb + HBL + (w * 8 + j) * 1024 + tb;
            ldsm4t(jb, B01);
            ldsm4t(jb + 512, B23);
#pragma unroll
            for (int mt = 0; mt < 2; mt++) {
                hmma(acc[mt][0], Ah[mt][j], B01);
                hmma(acc[mt][1], Ah[mt][j], B01 + 2);
                hmma(acc[mt][2], Ah[mt][j], B23);
                hmma(acc[mt][3], Ah[mt][j], B23 + 2);
            }
        }

        // store K-partials: Dp[w][m][b], pad 34
        {
            const int g = lane >> 2, c2 = (lane & 3) << 1;
            float* dpw = Dp + w * 1088;
#pragma unroll
            for (int mt = 0; mt < 2; mt++)
#pragma unroll
                for (int nt = 0; nt < 4; nt++) {
                    const int r0 = mt * 16 + g, c0 = nt * 8 + c2;
                    *(float2*)(dpw + r0 * 34 + c0) =
                        make_float2(acc[mt][nt][0], acc[mt][nt][1]);
                    *(float2*)(dpw + (r0 + 8) * 34 + c0) =
                        make_float2(acc[mt][nt][2], acc[mt][nt][3]);
                }
        }
        __syncthreads();

        // epilogue: thread (cell,b) reduces 8 partials x 4 gates
        {
            float s0 = xgv[0], s1 = xgv[1], s2 = xgv[2], s3 = xgv[3];
#pragma unroll
            for (int w2 = 0; w2 < 8; w2++) {
                const float* dpw = Dp + w2 * 1088 + cell * 34 + b;
                s0 += dpw[0];
                s1 += dpw[8 * 34];
                s2 += dpw[16 * 34];
                s3 += dpw[24 * 34];
            }
            const float si = 0.5f * (1.0f + tanhf(0.5f * s0));
            const float sf = 0.5f * (1.0f + tanhf(0.5f * s1));
            const float so = 0.5f * (1.0f + tanhf(0.5f * s3));
            cs = sf * cs + si * tanhf(s2);
            const float h = so * tanhf(cs);
            out[((size_t)b * TDIM + t) * HDIM + n] = h;

            unsigned short hh, hl; split_bf16(h, hh, hl);
            unsigned char* hd = g_hB[(t + 1) & 1];
            const uint32_t off = (uint32_t)((n >> 4) * 1024 + (b >> 3) * 256
                                 + (n & 15) * 16 + (b & 7) * 2);
            *(unsigned short*)(hd + off)         = hh;
            *(unsigned short*)(hd + 65536 + off) = hl;
        }

        if (t < TDIM - 1) {
            __threadfence();
            __syncthreads();
            if (tid == 0) {
                atomicAdd(&g_count, 1);
                while (ld_acquire(&g_count) < NBLK * (t + 1)) { }
            }
            __syncthreads();
        }
    }
}

// ---------------------------------------------------------------------------
extern "C" void kernel_launch(void* const* d_in, const int* in_sizes, int n_in,
                              void* d_out, int out_size)
{
    const float* x  = (const float*)d_in[0];
    const float* Wx = (const float*)d_in[1];
    const float* bx = (const float*)d_in[2];
    const float* Wh = (const float*)d_in[3];
    const float* bh = (const float*)d_in[4];
    float* out = (float*)d_out;
    (void)in_sizes; (void)n_in; (void)out_size;

    cudaFuncSetAttribute(lstm_hmma_kernel,
                         cudaFuncAttributeMaxDynamicSharedMemorySize, SMEM2);
    cudaFuncSetAttribute(gemm_hmma_kernel,
                         cudaFuncAttributeMaxDynamicSharedMemorySize, SMEM_G);

    prep_kernel<<<8192, 256>>>(Wh);
    prepA_kernel<<<16384, 256>>>(x);
    prepB_kernel<<<8192, 256>>>(Wx);

    dim3 ggrid(32, 128);
    gemm_hmma_kernel<<<ggrid, 256, SMEM_G>>>(bx, bh);

    lstm_hmma_kernel<<<NBLK, 256, SMEM2>>>(out);
}

// round 14
// speedup vs baseline: 2.6525x; 1.0716x over previous
#include <cuda_runtime.h>
#include <cuda_bf16.h>
#include <cstdint>

#define TDIM 512
#define IDIM 512
#define HDIM 1024
#define G4   4096
#define NBLK 128
#define HBH  0
#define HBL  65536
#define DPOFF 131072
#define SMEM2 165888
#define SMEM_G 65536

typedef unsigned long long ull;

__device__ float g_xg[(size_t)32 * TDIM * G4];
__device__ __align__(128) unsigned char g_W[(size_t)NBLK * 131072];
__device__ __align__(128) unsigned char g_hB[2][131072];
__device__ __align__(128) unsigned char g_AX[(size_t)128 * 16 * 16384];
__device__ __align__(128) unsigned char g_BW[(size_t)32 * 16 * 16384];
__device__ int g_count;

__device__ __forceinline__ int ld_acquire(const int* p) {
    int v; asm volatile("ld.global.acquire.gpu.b32 %0, [%1];" : "=r"(v) : "l"(p));
    return v;
}
__device__ __forceinline__ void red_release_add(int* p, int v) {
    asm volatile("red.release.gpu.global.add.s32 [%0], %1;" :: "l"(p), "r"(v) : "memory");
}
__device__ __forceinline__ void ldsm4(uint32_t a, uint32_t* r) {
    asm volatile("ldmatrix.sync.aligned.m8n8.x4.shared.b16 {%0,%1,%2,%3}, [%4];"
        : "=r"(r[0]), "=r"(r[1]), "=r"(r[2]), "=r"(r[3]) : "r"(a));
}
__device__ __forceinline__ void ldsm4t(uint32_t a, uint32_t* r) {
    asm volatile("ldmatrix.sync.aligned.m8n8.x4.trans.shared.b16 {%0,%1,%2,%3}, [%4];"
        : "=r"(r[0]), "=r"(r[1]), "=r"(r[2]), "=r"(r[3]) : "r"(a));
}
__device__ __forceinline__ void hmma(float* d, const uint32_t* a, const uint32_t* b) {
    asm volatile("mma.sync.aligned.m16n8k16.row.col.f32.bf16.bf16.f32 "
        "{%0,%1,%2,%3},{%4,%5,%6,%7},{%8,%9},{%0,%1,%2,%3};"
        : "+f"(d[0]), "+f"(d[1]), "+f"(d[2]), "+f"(d[3])
        : "r"(a[0]), "r"(a[1]), "r"(a[2]), "r"(a[3]), "r"(b[0]), "r"(b[1]));
}
__device__ __forceinline__ void cpa(uint32_t d, const void* s) {
    asm volatile("cp.async.cg.shared.global [%0], [%1], 16;" :: "r"(d), "l"(s) : "memory");
}
#define WAITG(N) asm volatile("cp.async.wait_group %0;" :: "n"(N) : "memory")
__device__ __forceinline__ void split_bf16(float v, unsigned short& hi, unsigned short& lo) {
    __nv_bfloat16 h = __float2bfloat16(v);
    __nv_bfloat16 l = __float2bfloat16(v - __bfloat162float(h));
    hi = *(unsigned short*)&h; lo = *(unsigned short*)&l;
}
__device__ __forceinline__ float sigx(float x) {
    return __fdividef(1.0f, 1.0f + __expf(-x));
}
__device__ __forceinline__ float tanhx(float x) {
    return 2.0f * __fdividef(1.0f, 1.0f + __expf(-2.0f * x)) - 1.0f;
}

// ---- prep: Wh -> step-kernel A images --------------------------------------
__global__ void __launch_bounds__(256) prep_kernel(const float* __restrict__ Wh) {
    const int e = blockIdx.x * 256 + threadIdx.x;
    const int blk = e >> 14, rem = e & 16383;
    const int m = rem >> 9, k = (rem & 511) * 2;
    const int row = ((m >> 3) << 10) + (blk << 3) + (m & 7);
    const float2 wv = *(const float2*)(Wh + (size_t)row * HDIM + k);
    unsigned short h0, l0, h1, l1;
    split_bf16(wv.x, h0, l0); split_bf16(wv.y, h1, l1);
    const int mt = m >> 4, r = m & 15, kt = k >> 4, kc = k & 15;
    const uint32_t off = (uint32_t)(mt * 32768 + kt * 512 + r * 32
                       + (((kc >> 3) ^ ((r >> 2) & 1)) << 4) + (kc & 7) * 2);
    unsigned char* base = g_W + (size_t)blk * 131072;
    *(uint32_t*)(base + off)         = (uint32_t)h0 | ((uint32_t)h1 << 16);
    *(uint32_t*)(base + 65536 + off) = (uint32_t)l0 | ((uint32_t)l1 << 16);
    if (e < 32768) ((uint32_t*)g_hB[0])[e] = 0u;
    if (e == 0) g_count = 0;
}

// ---- prep: X -> phase-1 A-images -------------------------------------------
__global__ void __launch_bounds__(256) prepA_kernel(const float* __restrict__ X) {
    const int e = blockIdx.x * 256 + threadIdx.x;
    const int k = (e & 255) * 2, m = e >> 8;
    const float2 xv = *(const float2*)(X + (size_t)m * IDIM + k);
    unsigned short h0, l0, h1, l1;
    split_bf16(xv.x, h0, l0); split_bf16(xv.y, h1, l1);
    const int R = m >> 7, rr = m & 127, mm = rr >> 4, r = rr & 15;
    const int kc = k >> 5, kt = (k >> 4) & 1, kcol = k & 15;
    unsigned char* base = g_AX + (size_t)(R * 16 + kc) * 16384 + kt * 8192 + mm * 512;
    const uint32_t off = (uint32_t)(r * 32 + (((kcol >> 3) ^ ((r >> 2) & 1)) << 4)
                       + (kcol & 7) * 2);
    *(uint32_t*)(base + off)        = (uint32_t)h0 | ((uint32_t)h1 << 16);
    *(uint32_t*)(base + 4096 + off) = (uint32_t)l0 | ((uint32_t)l1 << 16);
}

// ---- prep: Wx -> phase-1 B-images ------------------------------------------
__global__ void __launch_bounds__(256) prepB_kernel(const float* __restrict__ Wx) {
    const int e = blockIdx.x * 256 + threadIdx.x;
    const int k = e & 511, n = e >> 9;
    const float wv = Wx[(size_t)n * IDIM + k];
    unsigned short hi, lo; split_bf16(wv, hi, lo);
    const int NB = n >> 7, cc = n & 127, nt = cc >> 3, nn = cc & 7;
    const int kc = k >> 5, kt = (k >> 4) & 1, r = k & 15;
    unsigned char* base = g_BW + (size_t)(NB * 16 + kc) * 16384 + kt * 8192 + nt * 256;
    const uint32_t off = (uint32_t)(r * 16 + nn * 2);
    *(unsigned short*)(base + off)        = hi;
    *(unsigned short*)(base + 4096 + off) = lo;
}

// ---- Phase 1: HMMA GEMM, 2 CTAs/SM -----------------------------------------
__global__ void __launch_bounds__(256, 2) gemm_hmma_kernel(
    const float* __restrict__ bx, const float* __restrict__ bh)
{
    extern __shared__ unsigned char smc[];
    const uint32_t smb = (uint32_t)__cvta_generic_to_shared(smc);
    const int tid = threadIdx.x, lane = tid & 31, w = tid >> 5;
    const int mt = w & 3, nt = w >> 2;
    const int MB = blockIdx.y, NB = blockIdx.x;
    const unsigned char* srcA = g_AX + (size_t)MB * (16 * 16384);
    const unsigned char* srcB = g_BW + (size_t)NB * (16 * 16384);
    const int r = lane & 15, hb = lane >> 4;
    const uint32_t aSw = (uint32_t)(r * 32 + ((hb ^ ((r >> 2) & 1)) << 4));
    const uint32_t tb  = (uint32_t)(r * 16 + hb * 256);

    float acc[2][8][4];
#pragma unroll
    for (int i = 0; i < 2; i++)
#pragma unroll
        for (int j = 0; j < 8; j++)
#pragma unroll
            for (int q = 0; q < 4; q++) acc[i][j][q] = 0.0f;

#define LOADC(kc, s) { \
    _Pragma("unroll") for (int rd = 0; rd < 4; rd++) { \
        cpa(smb + (s) * 32768 + tid * 16 + rd * 4096, \
            srcA + (size_t)(kc) * 16384 + tid * 16 + rd * 4096); \
        cpa(smb + (s) * 32768 + 16384 + tid * 16 + rd * 4096, \
            srcB + (size_t)(kc) * 16384 + tid * 16 + rd * 4096); } \
    asm volatile("cp.async.commit_group;" ::: "memory"); }

    LOADC(0, 0)
    for (int kc = 0; kc < 16; kc++) {
        const int s = kc & 1;
        if (kc < 15) LOADC(kc + 1, 1 - s)
        if (kc < 15) { WAITG(1); } else { WAITG(0); }
        __syncthreads();
#pragma unroll
        for (int kt = 0; kt < 2; kt++) {
            const uint32_t ab = smb + s * 32768 + kt * 8192;
            const uint32_t bb = smb + s * 32768 + 16384 + kt * 8192 + tb;
            uint32_t Ah[2][4], Al[2][4];
#pragma unroll
            for (int i = 0; i < 2; i++) {
                ldsm4(ab + (2 * mt + i) * 512 + aSw, Ah[i]);
                ldsm4(ab + 4096 + (2 * mt + i) * 512 + aSw, Al[i]);
            }
#pragma unroll
            for (int jj = 0; jj < 4; jj++) {
                uint32_t Bh4[4], Bl4[4];
                ldsm4t(bb + (8 * nt + 2 * jj) * 256, Bh4);
                ldsm4t(bb + 4096 + (8 * nt + 2 * jj) * 256, Bl4);
#pragma unroll
                for (int sj = 0; sj < 2; sj++) {
                    const uint32_t* Bh = Bh4 + 2 * sj;
                    const uint32_t* Bl = Bl4 + 2 * sj;
#pragma unroll
                    for (int i = 0; i < 2; i++) {
                        hmma(acc[i][2 * jj + sj], Ah[i], Bh);
                        hmma(acc[i][2 * jj + sj], Al[i], Bh);
                        hmma(acc[i][2 * jj + sj], Ah[i], Bl);
                    }
                }
            }
        }
        __syncthreads();
    }
    const int g = lane >> 2, c2 = (lane & 3) << 1;
#pragma unroll
    for (int j = 0; j < 8; j++) {
        const int n0 = NB * 128 + nt * 64 + j * 8 + c2;
        const float2 bxv = *(const float2*)(bx + n0);
        const float2 bhv = *(const float2*)(bh + n0);
        const float b0 = bxv.x + bhv.x, b1 = bxv.y + bhv.y;
#pragma unroll
        for (int i = 0; i < 2; i++) {
            const int m0 = MB * 128 + mt * 32 + i * 16 + g;
            *(float2*)(g_xg + (size_t)m0 * G4 + n0) =
                make_float2(acc[i][j][0] + b0, acc[i][j][1] + b1);
            *(float2*)(g_xg + (size_t)(m0 + 8) * G4 + n0) =
                make_float2(acc[i][j][2] + b0, acc[i][j][3] + b1);
        }
    }
}

// ---- Phase 2: persistent HMMA recurrence ------------------------------------
__global__ void __launch_bounds__(256, 1) lstm_hmma_kernel(float* __restrict__ out)
{
    extern __shared__ unsigned char smc[];
    const uint32_t smb = (uint32_t)__cvta_generic_to_shared(smc);
    const int tid = threadIdx.x, lane = tid & 31, w = tid >> 5;
    const int r = lane & 15, hb = lane >> 4;

    {
        const unsigned char* src = g_W + (size_t)blockIdx.x * 131072;
#pragma unroll
        for (int cq = 0; cq < 32; cq++)
            cpa(smb + tid * 16 + cq * 4096, src + tid * 16 + cq * 4096);
        asm volatile("cp.async.commit_group;" ::: "memory");
        WAITG(0);
        __syncthreads();
    }
    uint32_t Ah[2][8][4], Al[2][8][4];
    {
        const uint32_t aSw = (uint32_t)(r * 32 + ((hb ^ ((r >> 2) & 1)) << 4));
#pragma unroll
        for (int mt = 0; mt < 2; mt++)
#pragma unroll
            for (int j = 0; j < 8; j++) {
                ldsm4(smb + mt * 32768 + (w * 8 + j) * 512 + aSw, Ah[mt][j]);
                ldsm4(smb + 65536 + mt * 32768 + (w * 8 + j) * 512 + aSw, Al[mt][j]);
            }
    }
    __syncthreads();

    float* Dp = (float*)(smc + DPOFF);
    const int cell = tid & 7, b = tid >> 3;
    const int n = blockIdx.x * 8 + cell;
    const uint32_t tb = (uint32_t)(r * 16 + hb * 256);
    float cs = 0.0f;

    float xgv[4];
    {
        const float* xp = g_xg + ((size_t)b * TDIM) * G4 + n;
#pragma unroll
        for (int g2 = 0; g2 < 4; g2++) xgv[g2] = __ldg(xp + g2 * HDIM);
    }

    for (int t = 0; t < TDIM; t++) {
        const unsigned char* hsrc = g_hB[t & 1];
        {
            const uint32_t dh = smb + HBH + w * 8192 + lane * 16;
            const uint32_t dl = smb + HBL + w * 8192 + lane * 16;
            const unsigned char* sh = hsrc + w * 8192 + lane * 16;
            const unsigned char* sl = hsrc + 65536 + w * 8192 + lane * 16;
#pragma unroll
            for (int q = 0; q < 16; q++) cpa(dh + q * 512, sh + q * 512);
            asm volatile("cp.async.commit_group;" ::: "memory");
#pragma unroll
            for (int q = 0; q < 16; q++) cpa(dl + q * 512, sl + q * 512);
            asm volatile("cp.async.commit_group;" ::: "memory");
        }

        float acc[2][4][4];
#pragma unroll
        for (int mt = 0; mt < 2; mt++)
#pragma unroll
            for (int nt = 0; nt < 4; nt++)
#pragma unroll
                for (int q = 0; q < 4; q++) acc[mt][nt][q] = 0.0f;

        WAITG(1); __syncwarp();
#pragma unroll
        for (int j = 0; j < 8; j++) {
            uint32_t B01[4], B23[4];
            const uint32_t jb = smb + HBH + (w * 8 + j) * 1024 + tb;
            ldsm4t(jb, B01);
            ldsm4t(jb + 512, B23);
#pragma unroll
            for (int mt = 0; mt < 2; mt++) {
                hmma(acc[mt][0], Ah[mt][j], B01);
                hmma(acc[mt][1], Ah[mt][j], B01 + 2);
                hmma(acc[mt][2], Ah[mt][j], B23);
                hmma(acc[mt][3], Ah[mt][j], B23 + 2);
                hmma(acc[mt][0], Al[mt][j], B01);
                hmma(acc[mt][1], Al[mt][j], B01 + 2);
                hmma(acc[mt][2], Al[mt][j], B23);
                hmma(acc[mt][3], Al[mt][j], B23 + 2);
            }
        }
        WAITG(0); __syncwarp();
#pragma unroll
        for (int j = 0; j < 8; j++) {
            uint32_t B01[4], B23[4];
            const uint32_t jb = smb + HBL + (w * 8 + j) * 1024 + tb;
            ldsm4t(jb, B01);
            ldsm4t(jb + 512, B23);
#pragma unroll
            for (int mt = 0; mt < 2; mt++) {
                hmma(acc[mt][0], Ah[mt][j], B01);
                hmma(acc[mt][1], Ah[mt][j], B01 + 2);
                hmma(acc[mt][2], Ah[mt][j], B23);
                hmma(acc[mt][3], Ah[mt][j], B23 + 2);
            }
        }

        {
            const int g = lane >> 2, c2 = (lane & 3) << 1;
            float* dpw = Dp + w * 1088;
#pragma unroll
            for (int mt = 0; mt < 2; mt++)
#pragma unroll
                for (int nt = 0; nt < 4; nt++) {
                    const int r0 = mt * 16 + g, c0 = nt * 8 + c2;
                    *(float2*)(dpw + r0 * 34 + c0) =
                        make_float2(acc[mt][nt][0], acc[mt][nt][1]);
                    *(float2*)(dpw + (r0 + 8) * 34 + c0) =
                        make_float2(acc[mt][nt][2], acc[mt][nt][3]);
                }
        }
        __syncthreads();

        {
            float s0 = xgv[0], s1 = xgv[1], s2 = xgv[2], s3 = xgv[3];
#pragma unroll
            for (int w2 = 0; w2 < 8; w2++) {
                const float* dpw = Dp + w2 * 1088 + cell * 34 + b;
                s0 += dpw[0];
                s1 += dpw[8 * 34];
                s2 += dpw[16 * 34];
                s3 += dpw[24 * 34];
            }
            const float si = sigx(s0);
            const float sf = sigx(s1);
            const float so = sigx(s3);
            cs = sf * cs + si * tanhx(s2);
            const float h = so * tanhx(cs);
            out[((size_t)b * TDIM + t) * HDIM + n] = h;

            unsigned short hh, hl; split_bf16(h, hh, hl);
            unsigned char* hd = g_hB[(t + 1) & 1];
            const uint32_t off = (uint32_t)((n >> 4) * 1024 + (b >> 3) * 256
                                 + (n & 15) * 16 + (b & 7) * 2);
            *(unsigned short*)(hd + off)         = hh;
            *(unsigned short*)(hd + 65536 + off) = hl;
        }

        if (t < TDIM - 1) {
            __syncthreads();                          // all h stores done (CTA HB)
            if (tid == 0) red_release_add(&g_count, 1);
            {   // prefetch next xg during the barrier wait
                const float* xp = g_xg + ((size_t)b * TDIM + (t + 1)) * G4 + n;
#pragma unroll
                for (int g2 = 0; g2 < 4; g2++) xgv[g2] = __ldg(xp + g2 * HDIM);
            }
            if (tid == 0)
                while (ld_acquire(&g_count) < NBLK * (t + 1)) { }
            __syncthreads();
        }
    }
}

// ---------------------------------------------------------------------------
extern "C" void kernel_launch(void* const* d_in, const int* in_sizes, int n_in,
                              void* d_out, int out_size)
{
    const float* x  = (const float*)d_in[0];
    const float* Wx = (const float*)d_in[1];
    const float* bx = (const float*)d_in[2];
    const float* Wh = (const float*)d_in[3];
    const float* bh = (const float*)d_in[4];
    float* out = (float*)d_out;
    (void)in_sizes; (void)n_in; (void)out_size;

    cudaFuncSetAttribute(lstm_hmma_kernel,
                         cudaFuncAttributeMaxDynamicSharedMemorySize, SMEM2);
    cudaFuncSetAttribute(gemm_hmma_kernel,
                         cudaFuncAttributeMaxDynamicSharedMemorySize, SMEM_G);

    prep_kernel<<<8192, 256>>>(Wh);
    prepA_kernel<<<16384, 256>>>(x);
    prepB_kernel<<<8192, 256>>>(Wx);

    dim3 ggrid(32, 128);
    gemm_hmma_kernel<<<ggrid, 256, SMEM_G>>>(bx, bh);

    lstm_hmma_kernel<<<NBLK, 256, SMEM2>>>(out);
}